// round 17
// baseline (speedup 1.0000x reference)
#include <cuda_runtime.h>
#include <cstdint>

#define BB 32
#define CC 256
#define HWL 3136                 // 56*56
#define HID 32
#define NPLANE (BB*CC)           // 8192
#define NHALF (NPLANE * 2)       // 16384
#define HALF_FLOATS 1568         // HWL/2
#define HALF_BYTES (HALF_FLOATS * 4)   // 6272
#define HALF_F4 (HALF_FLOATS / 4)      // 392 = 6*64 + 8

__device__ float g_part[NHALF];      // per-half sums
__device__ float g_a0[NPLANE];
__device__ float g_c0[NPLANE];
__device__ float g_a1[NPLANE];
__device__ float g_c1[NPLANE];

__device__ __forceinline__ uint32_t smem_u32(const void* p) {
    return (uint32_t)__cvta_generic_to_shared(p);
}

// ---------------------------------------------------------------------------
// Kernel 1: TMA swarm pool at HALF-plane granularity. Grid 16384, 64 thr,
// 6.4 KB smem -> 32 CTAs/SM (the HW slot cap): ~2x in-flight reads vs R16.
// ---------------------------------------------------------------------------
__global__ __launch_bounds__(64) void pool_half_kernel(const float* __restrict__ x) {
    __shared__ alignas(16) float tile[HALF_FLOATS];
    __shared__ alignas(8) unsigned long long mbar;
    __shared__ float ws[2];

    const int idx = blockIdx.x;          // half index
    const int plane = idx >> 1;
    const int half = idx & 1;
    const int tid = threadIdx.x;
    const int lane = tid & 31;
    const int warp = tid >> 5;
    const uint32_t mb = smem_u32(&mbar);
    const uint32_t ta = smem_u32(tile);

    if (tid == 0) {
        asm volatile("mbarrier.init.shared.b64 [%0], 1;" :: "r"(mb) : "memory");
        asm volatile("mbarrier.arrive.expect_tx.shared.b64 _, [%0], %1;"
                     :: "r"(mb), "r"((uint32_t)HALF_BYTES) : "memory");
        asm volatile(
            "cp.async.bulk.shared::cluster.global.mbarrier::complete_tx::bytes "
            "[%0], [%1], %2, [%3];"
            :: "r"(ta),
               "l"(x + (size_t)plane * HWL + (size_t)half * HALF_FLOATS),
               "r"((uint32_t)HALF_BYTES), "r"(mb) : "memory");
    }
    __syncthreads();

    asm volatile(
        "{\n\t"
        ".reg .pred P;\n\t"
        "W_%=:\n\t"
        "mbarrier.try_wait.parity.shared.b64 P, [%0], 0;\n\t"
        "@!P bra W_%=;\n\t"
        "}"
        :: "r"(mb) : "memory");

    const float4* t4 = reinterpret_cast<const float4*>(tile);
    float s = 0.f;
#pragma unroll
    for (int k = 0; k < 6; k++) {
        float4 v = t4[tid + 64 * k];
        s += (v.x + v.y) + (v.z + v.w);
    }
    if (tid < 8) {
        float4 v = t4[384 + tid];
        s += (v.x + v.y) + (v.z + v.w);
    }
#pragma unroll
    for (int o = 16; o > 0; o >>= 1) s += __shfl_xor_sync(0xffffffffu, s, o);
    if (lane == 0) ws[warp] = s;
    __syncthreads();
    if (tid == 0) g_part[idx] = ws[0] + ws[1];
}

// ---------------------------------------------------------------------------
// Kernel 2: tiny MLP -> per-plane coefficient tables (sums the two halves).
// ---------------------------------------------------------------------------
__global__ __launch_bounds__(256) void coef_kernel(const float* __restrict__ fc1_w,
                                                   const float* __restrict__ fc1_b,
                                                   const float* __restrict__ fc2_w,
                                                   const float* __restrict__ fc2_b) {
    const int b = blockIdx.x;
    __shared__ float p_s[CC];
    __shared__ float h_s[HID];

    {
        const int pl = b * CC + threadIdx.x;
        p_s[threadIdx.x] = (g_part[2 * pl] + g_part[2 * pl + 1]) * (1.0f / HWL);
    }
    __syncthreads();

    {
        const int j = threadIdx.x >> 3;
        const int part = threadIdx.x & 7;
        const float* wrow = fc1_w + j * CC + part * 32;
        const float* pp = p_s + part * 32;
        float acc = 0.f;
#pragma unroll
        for (int i2 = 0; i2 < 32; i2++) acc = fmaf(pp[i2], wrow[i2], acc);
#pragma unroll
        for (int o = 4; o > 0; o >>= 1) acc += __shfl_down_sync(0xffffffffu, acc, o, 8);
        if (part == 0) h_s[j] = fmaxf(acc + fc1_b[j], 0.f);
    }
    __syncthreads();

    const int c = threadIdx.x;
    const float* wa0 = fc2_w + (size_t)(2 * c) * HID;
    const float* wb0 = wa0 + HID;
    const float* wa1 = fc2_w + (size_t)(2 * CC + 2 * c) * HID;
    const float* wb1 = wa1 + HID;
    float da0 = fc2_b[2 * c];
    float db0 = fc2_b[2 * c + 1];
    float da1 = fc2_b[2 * CC + 2 * c];
    float db1 = fc2_b[2 * CC + 2 * c + 1];
#pragma unroll
    for (int j = 0; j < HID; j++) {
        float hj = h_s[j];
        da0 = fmaf(wa0[j], hj, da0);
        db0 = fmaf(wb0[j], hj, db0);
        da1 = fmaf(wa1[j], hj, da1);
        db1 = fmaf(wb1[j], hj, db1);
    }
    const int plane = b * CC + c;
    g_a0[plane] = 1.0f + tanhf(0.5f * da0);          // LAMBDA_ALPHA = 1.0
    g_c0[plane] = 1.0f + 0.5f * tanhf(0.5f * db0);   // LAMBDA_BETA  = 0.5
    g_a1[plane] = tanhf(0.5f * da1);
    g_c1[plane] = 0.5f * tanhf(0.5f * db1);
}

// ---------------------------------------------------------------------------
// Kernel 3: TMA swarm apply at HALF-plane granularity. Grid 16384, 64 thr,
// 32 CTAs/SM. Reverse order + evict-first store retained.
// ---------------------------------------------------------------------------
__global__ __launch_bounds__(64) void apply_half_kernel(const float* __restrict__ x,
                                                        float* __restrict__ out) {
    __shared__ alignas(16) float tile[HALF_FLOATS];
    __shared__ alignas(8) unsigned long long mbar;

    const int idx = (NHALF - 1) - blockIdx.x;   // reverse traversal
    const int plane = idx >> 1;
    const int half = idx & 1;
    const int tid = threadIdx.x;
    const uint32_t mb = smem_u32(&mbar);
    const uint32_t ta = smem_u32(tile);
    const size_t goff = (size_t)plane * HWL + (size_t)half * HALF_FLOATS;

    if (tid == 0) {
        asm volatile("mbarrier.init.shared.b64 [%0], 1;" :: "r"(mb) : "memory");
        asm volatile("mbarrier.arrive.expect_tx.shared.b64 _, [%0], %1;"
                     :: "r"(mb), "r"((uint32_t)HALF_BYTES) : "memory");
        asm volatile(
            "cp.async.bulk.shared::cluster.global.mbarrier::complete_tx::bytes "
            "[%0], [%1], %2, [%3];"
            :: "r"(ta), "l"(x + goff),
               "r"((uint32_t)HALF_BYTES), "r"(mb) : "memory");
    }
    __syncthreads();

    const float a0 = g_a0[plane];
    const float c0 = g_c0[plane];
    const float a1 = g_a1[plane];
    const float c1 = g_c1[plane];

    asm volatile(
        "{\n\t"
        ".reg .pred P;\n\t"
        "W_%=:\n\t"
        "mbarrier.try_wait.parity.shared.b64 P, [%0], 0;\n\t"
        "@!P bra W_%=;\n\t"
        "}"
        :: "r"(mb) : "memory");

    float4* t4 = reinterpret_cast<float4*>(tile);
#pragma unroll
    for (int k = 0; k < 6; k++) {
        float4 v = t4[tid + 64 * k];
        float4 r;
        r.x = fmaxf(fmaf(v.x, a0, c0), fmaf(v.x, a1, c1));
        r.y = fmaxf(fmaf(v.y, a0, c0), fmaf(v.y, a1, c1));
        r.z = fmaxf(fmaf(v.z, a0, c0), fmaf(v.z, a1, c1));
        r.w = fmaxf(fmaf(v.w, a0, c0), fmaf(v.w, a1, c1));
        t4[tid + 64 * k] = r;
    }
    if (tid < 8) {
        float4 v = t4[384 + tid];
        float4 r;
        r.x = fmaxf(fmaf(v.x, a0, c0), fmaf(v.x, a1, c1));
        r.y = fmaxf(fmaf(v.y, a0, c0), fmaf(v.y, a1, c1));
        r.z = fmaxf(fmaf(v.z, a0, c0), fmaf(v.z, a1, c1));
        r.w = fmaxf(fmaf(v.w, a0, c0), fmaf(v.w, a1, c1));
        t4[384 + tid] = r;
    }
    __syncthreads();

    if (tid == 0) {
        asm volatile("fence.proxy.async.shared::cta;" ::: "memory");
        asm volatile(
            "{\n\t"
            ".reg .b64 pol;\n\t"
            "createpolicy.fractional.L2::evict_first.b64 pol, 1.0;\n\t"
            "cp.async.bulk.global.shared::cta.bulk_group.L2::cache_hint "
            "[%0], [%1], %2, pol;\n\t"
            "}"
            :: "l"(out + goff), "r"(ta),
               "r"((uint32_t)HALF_BYTES) : "memory");
        asm volatile("cp.async.bulk.commit_group;" ::: "memory");
        asm volatile("cp.async.bulk.wait_group 0;" ::: "memory");
    }
}

extern "C" void kernel_launch(void* const* d_in, const int* in_sizes, int n_in,
                              void* d_out, int out_size) {
    const float* x      = (const float*)d_in[0];
    const float* fc1_w  = (const float*)d_in[1];
    const float* fc1_b  = (const float*)d_in[2];
    const float* fc2_w  = (const float*)d_in[3];
    const float* fc2_b  = (const float*)d_in[4];
    float* out = (float*)d_out;

    static bool configured = false;
    if (!configured) {
        cudaFuncSetAttribute(pool_half_kernel,
                             cudaFuncAttributePreferredSharedMemoryCarveout, 100);
        cudaFuncSetAttribute(apply_half_kernel,
                             cudaFuncAttributePreferredSharedMemoryCarveout, 100);
        configured = true;
    }

    pool_half_kernel<<<NHALF, 64>>>(x);
    coef_kernel<<<BB, 256>>>(fc1_w, fc1_b, fc2_w, fc2_b);
    apply_half_kernel<<<NHALF, 64>>>(x, out);
}